// round 9
// baseline (speedup 1.0000x reference)
#include <cuda_runtime.h>
#include <cuda_bf16.h>
#include <cuda_fp16.h>
#include <cstdint>

#define N_NODES 100000
#define N_EDGES 1600000
#define D 128
#define NT64 ((N_NODES + 63) / 64)        /* 1563 tiles of 64 rows */
#define SCAN_NB ((N_NODES + 1023) / 1024) /* 98 */

// ---------------- scratch (static device arrays; no allocations) -------------
__device__ int    g_off[N_NODES + 1];
__device__ int    g_cursor[N_NODES];
__device__ int    g_part[SCAN_NB];
__device__ int    g_scol[N_EDGES];
__device__ float  g_agg[(size_t)N_NODES * D];
__device__ __half g_xh[(size_t)N_NODES * D];   // fp16 copy of x for gather
__device__ uint4  g_bimg[8480];                // prebuilt smem image: bias+Bhi+Blo

// ======================= PTX helpers (baseline sm_100) =======================
__device__ __forceinline__ uint32_t smem_u32(const void* p) {
    uint32_t a;
    asm("{ .reg .u64 t; cvta.to.shared.u64 t, %1; cvt.u32.u64 %0, t; }"
        : "=r"(a) : "l"(p));
    return a;
}
// pack two floats to bf16x2: low 16 bits = bf16(lo), high 16 = bf16(hi)
__device__ __forceinline__ uint32_t packbf(float lo, float hi) {
    uint32_t r;
    asm("cvt.rn.bf16x2.f32 %0, %1, %2;" : "=r"(r) : "f"(hi), "f"(lo));
    return r;
}
#define LDSM_X4(r, addr)                                                          \
    asm volatile("ldmatrix.sync.aligned.m8n8.x4.shared.b16 {%0,%1,%2,%3}, [%4];" \
                 : "=r"((r)[0]), "=r"((r)[1]), "=r"((r)[2]), "=r"((r)[3])        \
                 : "r"(addr))
#define LDSM_X2(r, addr)                                                          \
    asm volatile("ldmatrix.sync.aligned.m8n8.x2.shared.b16 {%0,%1}, [%2];"       \
                 : "=r"((r)[0]), "=r"((r)[1])                                    \
                 : "r"(addr))
#define MMA_BF16(d, a, b)                                                         \
    asm volatile("mma.sync.aligned.m16n8k16.row.col.f32.bf16.bf16.f32 "          \
                 "{%0,%1,%2,%3}, {%4,%5,%6,%7}, {%8,%9}, {%0,%1,%2,%3};"         \
                 : "+f"((d)[0]), "+f"((d)[1]), "+f"((d)[2]), "+f"((d)[3])        \
                 : "r"((a)[0]), "r"((a)[1]), "r"((a)[2]), "r"((a)[3]),           \
                   "r"((b)[0]), "r"((b)[1]))

// ---------------- k_init: fused zero + B-image prep + x->fp16 convert --------
// blocks [0,391): zero g_off; [391,519): build B image; [519,13019): cvt x.
#define INIT_ZB 391
#define INIT_PB 128
#define INIT_CB 12500
__global__ void k_init(const float* __restrict__ x, const float* __restrict__ w,
                       const float* __restrict__ root,
                       const float* __restrict__ bias) {
    int bid = blockIdx.x, tid = threadIdx.x;
    if (bid < INIT_ZB) {
        int i = bid * 256 + tid;
        if (i < N_NODES) g_off[i] = 0;
        if (i == N_NODES) g_off[N_NODES] = N_EDGES;   // total is a constant
    } else if (bid < INIT_ZB + INIT_PB) {
        int idx = (bid - INIT_ZB) * 256 + tid;
        char* img = (char*)g_bimg;
        if (idx < 256 * 128) {
            int k = idx >> 7, n = idx & 127;
            float v = (k < 128) ? w[(k << 7) + n] : root[((k - 128) << 7) + n];
            __nv_bfloat16 h = __float2bfloat16(v);
            float rl = v - __bfloat162float(h);
            *(__nv_bfloat16*)(img + 512 + (n * 264 + k) * 2) = h;
            *(__nv_bfloat16*)(img + 512 + 67584 + (n * 264 + k) * 2) =
                __float2bfloat16(rl);
        }
        if (bid == INIT_ZB && tid < 128)
            ((float*)img)[tid] = bias[tid];
    } else {
        size_t i = (size_t)(bid - INIT_ZB - INIT_PB) * 256 + tid;
        if (i < (size_t)N_NODES * 32) {
            float4 v = ((const float4*)x)[i];
            __half2 h0 = __floats2half2_rn(v.x, v.y);
            __half2 h1 = __floats2half2_rn(v.z, v.w);
            uint2 u;
            u.x = *reinterpret_cast<uint32_t*>(&h0);
            u.y = *reinterpret_cast<uint32_t*>(&h1);
            ((uint2*)g_xh)[i] = u;
        }
    }
}

// ---------------- k1: histogram (int4-vectorized; edge_index is int32) -------
__global__ void k_hist4(const int* __restrict__ ei) {
    int t = blockIdx.x * blockDim.x + threadIdx.x;
    if (t < N_EDGES / 4) {
        int4 r = ((const int4*)ei)[t];
        atomicAdd(&g_off[r.x], 1);
        atomicAdd(&g_off[r.y], 1);
        atomicAdd(&g_off[r.z], 1);
        atomicAdd(&g_off[r.w], 1);
    }
}

// ---------------- scan stage a: per-block sums --------------------------------
__global__ void k_scan_a() {
    __shared__ int ws[32];
    int tid = threadIdx.x, lane = tid & 31, wid = tid >> 5;
    int i = blockIdx.x * 1024 + tid;
    int v = (i < N_NODES) ? g_off[i] : 0;
    #pragma unroll
    for (int o = 16; o > 0; o >>= 1) v += __shfl_down_sync(0xffffffffu, v, o);
    if (lane == 0) ws[wid] = v;
    __syncthreads();
    if (wid == 0) {
        int t = ws[lane];
        #pragma unroll
        for (int o = 16; o > 0; o >>= 1) t += __shfl_down_sync(0xffffffffu, t, o);
        if (lane == 0) g_part[blockIdx.x] = t;
    }
}

// ---------------- scan stage c2: local scan of partials + apply ---------------
// Every block redundantly scans the 98 block sums (warp 0, 4 vals/lane), then
// applies its own prefix — removes the middle scan kernel entirely.
__global__ void k_scan_c2() {
    __shared__ int ws[32];
    __shared__ int spart[128];
    int tid = threadIdx.x, lane = tid & 31, wid = tid >> 5;
    if (wid == 0) {
        int v0 = (lane * 4 + 0 < SCAN_NB) ? g_part[lane * 4 + 0] : 0;
        int v1 = (lane * 4 + 1 < SCAN_NB) ? g_part[lane * 4 + 1] : 0;
        int v2 = (lane * 4 + 2 < SCAN_NB) ? g_part[lane * 4 + 2] : 0;
        int v3 = (lane * 4 + 3 < SCAN_NB) ? g_part[lane * 4 + 3] : 0;
        int sum = v0 + v1 + v2 + v3;
        int xs = sum;
        #pragma unroll
        for (int o = 1; o < 32; o <<= 1) {
            int t = __shfl_up_sync(0xffffffffu, xs, o);
            if (lane >= o) xs += t;
        }
        int run = xs - sum;   // exclusive prefix of this lane's group
        spart[lane * 4 + 0] = run; run += v0;
        spart[lane * 4 + 1] = run; run += v1;
        spart[lane * 4 + 2] = run; run += v2;
        spart[lane * 4 + 3] = run;
    }
    __syncthreads();
    int i = blockIdx.x * 1024 + tid;
    int v = (i < N_NODES) ? g_off[i] : 0;
    int xs = v;
    #pragma unroll
    for (int o = 1; o < 32; o <<= 1) {
        int t = __shfl_up_sync(0xffffffffu, xs, o);
        if (lane >= o) xs += t;
    }
    if (lane == 31) ws[wid] = xs;
    __syncthreads();
    if (wid == 0) {
        int t = ws[lane];
        #pragma unroll
        for (int o = 1; o < 32; o <<= 1) {
            int u = __shfl_up_sync(0xffffffffu, t, o);
            if (lane >= o) t += u;
        }
        ws[lane] = t;
    }
    __syncthreads();
    int excl = spart[blockIdx.x] + ((wid == 0) ? 0 : ws[wid - 1]) + xs - v;
    if (i < N_NODES) { g_off[i] = excl; g_cursor[i] = excl; }
}

// ---------------- k3: bucket source cols (int4-vectorized) -------------------
__global__ void k_scatter4(const int* __restrict__ ei) {
    int t = blockIdx.x * blockDim.x + threadIdx.x;
    if (t < N_EDGES / 4) {
        int4 r = ((const int4*)ei)[t];
        int4 c = ((const int4*)(ei + N_EDGES))[t];
        int p0 = atomicAdd(&g_cursor[r.x], 1);
        int p1 = atomicAdd(&g_cursor[r.y], 1);
        int p2 = atomicAdd(&g_cursor[r.z], 1);
        int p3 = atomicAdd(&g_cursor[r.w], 1);
        g_scol[p0] = c.x; g_scol[p1] = c.y;
        g_scol[p2] = c.z; g_scol[p3] = c.w;
    }
}

// ---------------- k4: fp16 gather-reduce, 16 lanes per edge ------------------
// One warp per node. Each half-warp serves one edge per load (uint4 = 16B/lane,
// 256B per edge) -> 2 edges per LDG instruction per warp, 4 edges in flight.
__global__ void k_agg() {
    int gw = (blockIdx.x * blockDim.x + threadIdx.x) >> 5;
    int lane = threadIdx.x & 31;
    if (gw >= N_NODES) return;
    int half = lane >> 4, hl = lane & 15;
    int s = g_off[gw], e = g_off[gw + 1];
    const uint4* xs = (const uint4*)g_xh;    // row = node*16 uint4s
    float a0[8], a1[8];
    #pragma unroll
    for (int q = 0; q < 8; q++) { a0[q] = 0.f; a1[q] = 0.f; }
    int j = s + half;
    for (; j + 2 < e; j += 4) {              // this half-warp: edges j, j+2
        int c0 = g_scol[j], c1 = g_scol[j + 2];
        uint4 u0 = xs[(size_t)c0 * 16 + hl];
        uint4 u1 = xs[(size_t)c1 * 16 + hl];
        float2 f;
        f = __half22float2(*reinterpret_cast<__half2*>(&u0.x)); a0[0] += f.x; a0[1] += f.y;
        f = __half22float2(*reinterpret_cast<__half2*>(&u0.y)); a0[2] += f.x; a0[3] += f.y;
        f = __half22float2(*reinterpret_cast<__half2*>(&u0.z)); a0[4] += f.x; a0[5] += f.y;
        f = __half22float2(*reinterpret_cast<__half2*>(&u0.w)); a0[6] += f.x; a0[7] += f.y;
        f = __half22float2(*reinterpret_cast<__half2*>(&u1.x)); a1[0] += f.x; a1[1] += f.y;
        f = __half22float2(*reinterpret_cast<__half2*>(&u1.y)); a1[2] += f.x; a1[3] += f.y;
        f = __half22float2(*reinterpret_cast<__half2*>(&u1.z)); a1[4] += f.x; a1[5] += f.y;
        f = __half22float2(*reinterpret_cast<__half2*>(&u1.w)); a1[6] += f.x; a1[7] += f.y;
    }
    if (j < e) {
        int c0 = g_scol[j];
        uint4 u0 = xs[(size_t)c0 * 16 + hl];
        float2 f;
        f = __half22float2(*reinterpret_cast<__half2*>(&u0.x)); a0[0] += f.x; a0[1] += f.y;
        f = __half22float2(*reinterpret_cast<__half2*>(&u0.y)); a0[2] += f.x; a0[3] += f.y;
        f = __half22float2(*reinterpret_cast<__half2*>(&u0.z)); a0[4] += f.x; a0[5] += f.y;
        f = __half22float2(*reinterpret_cast<__half2*>(&u0.w)); a0[6] += f.x; a0[7] += f.y;
    }
    #pragma unroll
    for (int q = 0; q < 8; q++) {
        a0[q] += a1[q];
        a0[q] += __shfl_down_sync(0xffffffffu, a0[q], 16);
    }
    if (half == 0) {                          // lanes 0-15 write cols hl*8..+7
        float inv = 1.0f / fmaxf((float)(e - s), 1.0f);
        float* o = g_agg + (size_t)gw * D + hl * 8;
        *(float4*)o = make_float4(a0[0] * inv, a0[1] * inv, a0[2] * inv, a0[3] * inv);
        *(float4*)(o + 4) = make_float4(a0[4] * inv, a0[5] * inv, a0[6] * inv, a0[7] * inv);
    }
}

// ---------------- k5: mma.sync bf16 split GEMM  out = [agg|x]@[W;root]+bias --
// (unchanged from R8 — proven rel_err 5.2e-5)
#define BS_STRIDE 264
#define AS_STRIDE 72
#define SO_BIAS 0
#define SO_BHI  512
#define SO_BLO  (SO_BHI + 128 * BS_STRIDE * 2)          /* 68096 */
#define SO_AHI  (SO_BLO + 128 * BS_STRIDE * 2)          /* 135680 */
#define SO_ALO  (SO_AHI + 64 * AS_STRIDE * 2)
#define SMEM_GEMM (SO_ALO + 64 * AS_STRIDE * 2)
#define BIMG_U4 (SO_AHI / 16)                           /* 8480 */

__global__ void __launch_bounds__(256, 1) k_gemm_mma(
    const float* __restrict__ x, float* __restrict__ out) {
    extern __shared__ char smem[];
    uint32_t sb = smem_u32(smem);
    float* sBias = (float*)(smem + SO_BIAS);
    int tid = threadIdx.x, lane = tid & 31, wid = tid >> 5;

    for (int i = tid; i < BIMG_U4; i += 256)
        ((uint4*)smem)[i] = g_bimg[i];
    __syncthreads();

    const int g = lane >> 2, tg = lane & 3;
    const int wm = wid >> 2, wn = wid & 3;       // 2 x 4 warp grid
    const int mbase_w = wm * 32, nbase_w = wn * 32;

    const uint32_t aAddrBase =
        sb + SO_AHI + (uint32_t)(mbase_w + (lane & 15)) * (AS_STRIDE * 2) +
        (uint32_t)(lane >> 4) * 16;
    const uint32_t bAddrBase =
        sb + SO_BHI + (uint32_t)(nbase_w + (lane & 7)) * (BS_STRIDE * 2) +
        (uint32_t)((lane >> 3) & 1) * 16;
    const uint32_t ALO_OFF = SO_ALO - SO_AHI;
    const uint32_t BLO_OFF = SO_BLO - SO_BHI;

    const int srow = tid >> 2, sq = tid & 3;

    for (int tile = blockIdx.x; tile < NT64; tile += gridDim.x) {
        int rb = tile * 64;
        float acc[2][4][4];
        #pragma unroll
        for (int mt = 0; mt < 2; mt++)
            #pragma unroll
            for (int nt = 0; nt < 4; nt++)
                #pragma unroll
                for (int q = 0; q < 4; q++) acc[mt][nt][q] = 0.f;

        #pragma unroll 1
        for (int kc = 0; kc < 4; kc++) {
            {   // stage A chunk: rows rb..rb+63, k cols kc*64..+63
                int gr = rb + srow;
                bool valid = gr < N_NODES;
                const float* src = (kc < 2)
                    ? (g_agg + (size_t)gr * D + kc * 64)
                    : (x + (size_t)gr * D + (kc - 2) * 64);
                #pragma unroll
                for (int p = 0; p < 4; p++) {
                    int col = (sq + p * 4) * 4;          // 0..60, step 16
                    float4 v = valid ? *(const float4*)(src + col)
                                     : make_float4(0.f, 0.f, 0.f, 0.f);
                    uint32_t h0 = packbf(v.x, v.y);
                    uint32_t h1 = packbf(v.z, v.w);
                    float r0 = v.x - __uint_as_float(h0 << 16);
                    float r1 = v.y - __uint_as_float(h0 & 0xffff0000u);
                    float r2 = v.z - __uint_as_float(h1 << 16);
                    float r3 = v.w - __uint_as_float(h1 & 0xffff0000u);
                    uint32_t l0 = packbf(r0, r1);
                    uint32_t l1 = packbf(r2, r3);
                    char* base = smem + (srow * AS_STRIDE + col) * 2;
                    *(uint2*)(base + SO_AHI) = make_uint2(h0, h1);
                    *(uint2*)(base + SO_ALO) = make_uint2(l0, l1);
                }
            }
            __syncthreads();

            #pragma unroll
            for (int k16 = 0; k16 < 4; k16++) {
                uint32_t bh[4][2], bl[4][2];
                uint32_t bcol = (uint32_t)(kc * 64 + k16 * 16) * 2;
                #pragma unroll
                for (int nt = 0; nt < 4; nt++) {
                    uint32_t ba = bAddrBase + (uint32_t)nt * (8 * BS_STRIDE * 2) + bcol;
                    LDSM_X2(bh[nt], ba);
                    LDSM_X2(bl[nt], ba + BLO_OFF);
                }
                #pragma unroll
                for (int mt = 0; mt < 2; mt++) {
                    uint32_t ah[4], al[4];
                    uint32_t aa = aAddrBase + (uint32_t)mt * (16 * AS_STRIDE * 2) +
                                  (uint32_t)k16 * 32;
                    LDSM_X4(ah, aa);
                    LDSM_X4(al, aa + ALO_OFF);
                    #pragma unroll
                    for (int nt = 0; nt < 4; nt++) {
                        MMA_BF16(acc[mt][nt], ah, bh[nt]);
                        MMA_BF16(acc[mt][nt], ah, bl[nt]);
                        MMA_BF16(acc[mt][nt], al, bh[nt]);
                    }
                }
            }
            __syncthreads();
        }

        #pragma unroll
        for (int mt = 0; mt < 2; mt++) {
            int r0 = rb + mbase_w + mt * 16 + g;
            #pragma unroll
            for (int nt = 0; nt < 4; nt++) {
                int col = nbase_w + nt * 8 + tg * 2;
                float b0 = sBias[col], b1 = sBias[col + 1];
                if (r0 < N_NODES)
                    *(float2*)(out + (size_t)r0 * D + col) =
                        make_float2(acc[mt][nt][0] + b0, acc[mt][nt][1] + b1);
                int r1 = r0 + 8;
                if (r1 < N_NODES)
                    *(float2*)(out + (size_t)r1 * D + col) =
                        make_float2(acc[mt][nt][2] + b0, acc[mt][nt][3] + b1);
            }
        }
    }
}

// ---------------- launch ------------------------------------------------------
extern "C" void kernel_launch(void* const* d_in, const int* in_sizes, int n_in,
                              void* d_out, int out_size) {
    const float* x    = (const float*)d_in[0];
    const int*   ei   = (const int*)d_in[1];     // int32 edge_index [2, E]
    const float* w    = (const float*)d_in[2];
    const float* root = (const float*)d_in[3];
    const float* bias = (const float*)d_in[4];
    float* out = (float*)d_out;

    (void)in_sizes; (void)n_in; (void)out_size;

    cudaFuncSetAttribute(k_gemm_mma, cudaFuncAttributeMaxDynamicSharedMemorySize,
                         SMEM_GEMM);

    k_init<<<INIT_ZB + INIT_PB + INIT_CB, 256>>>(x, w, root, bias);
    k_hist4<<<(N_EDGES / 4 + 255) / 256, 256>>>(ei);
    k_scan_a<<<SCAN_NB, 1024>>>();
    k_scan_c2<<<SCAN_NB, 1024>>>();
    k_scatter4<<<(N_EDGES / 4 + 255) / 256, 256>>>(ei);
    k_agg<<<(N_NODES * 32 + 255) / 256, 256>>>();
    k_gemm_mma<<<148, 256, SMEM_GEMM>>>(x, out);
}